// round 3
// baseline (speedup 1.0000x reference)
#include <cuda_runtime.h>

// ---------------------------------------------------------------------------
// Problem constants
// ---------------------------------------------------------------------------
#define NOSC 704          // 64 delta + 128 theta + 512 gamma
#define NPER 22           // oscillators per lane (704 / 32)
#define NCLS 1000
#define KDIM 704
#define NSAMP 65536

// Scratch for the rate matrix (65536 x 704 fp32 = 184.5 MB). Static __device__
// array: the sanctioned no-alloc scratch mechanism.
__device__ float g_rate[(size_t)NSAMP * NOSC];

// ---------------------------------------------------------------------------
// Helpers
// ---------------------------------------------------------------------------
__device__ __forceinline__ float warp_sum(float v) {
#pragma unroll
    for (int off = 16; off; off >>= 1) v += __shfl_xor_sync(0xffffffffu, v, off);
    return v;
}

__device__ __forceinline__ void ffma2(unsigned long long& d, unsigned long long a,
                                      unsigned long long b) {
    asm("fma.rn.f32x2 %0, %1, %2, %0;" : "+l"(d) : "l"(a), "l"(b));
}

__device__ __forceinline__ unsigned long long dup2(float v) {
    unsigned long long r;
    asm("mov.b64 %0, {%1, %1};" : "=l"(r) : "f"(v));
    return r;
}

__device__ __forceinline__ float2 unpk(unsigned long long v) {
    float lo, hi;
    asm("mov.b64 {%0, %1}, %2;" : "=f"(lo), "=f"(hi) : "l"(v));
    return make_float2(lo, hi);
}

// ---------------------------------------------------------------------------
// Kernel 1: oscillator dynamics + soft top-10% gate -> g_rate
// One warp per sample; all oscillator state in registers (22 per lane).
// Phase tracked as (cos, sin) unit vector; per-step rotation = constant
// rotation by dt*2*pi*f (precomputed in shared) composed with a small-angle
// 3rd-order polynomial rotation for the Kuramoto coupling term
// (|angle| <= 0.028 rad -> error < 4e-6 rad over 5 steps).
// ---------------------------------------------------------------------------
__global__ __launch_bounds__(256, 2) void dyn_kernel(const float* __restrict__ x,
                                                     const float* __restrict__ p0) {
    __shared__ float2 w0[NOSC];  // (cos, sin) of dt*2*pi*f per oscillator

    const int t = threadIdx.x;
    for (int i = t; i < NOSC; i += 256) {
        float f;
        if (i < 64)       f = 1.0f  + 3.0f  * (float)i         * (1.0f / 63.0f);
        else if (i < 192) f = 4.0f  + 4.0f  * (float)(i - 64)  * (1.0f / 127.0f);
        else              f = 30.0f + 50.0f * (float)(i - 192) * (1.0f / 511.0f);
        const float a0 = 0.01f * (6.283185307179586f * f);
        float sn, cs;
        sincosf(a0, &sn, &cs);  // precise version; once per block, cheap
        w0[i] = make_float2(cs, sn);
    }
    __syncthreads();

    const int lane = t & 31;
    const int warp = t >> 5;
    const int sample = blockIdx.x * 8 + warp;
    const float* xr = x  + (size_t)sample * NOSC;
    const float* pr = p0 + (size_t)sample * NOSC;

    float c[NPER], s[NPER], a[NPER];
#pragma unroll
    for (int k = 0; k < NPER; k++) {
        const int o = k * 32 + lane;
        const float ph = pr[o] * 6.2831853071795864f;
        __sincosf(ph, &s[k], &c[k]);
        a[k] = fmaf(fabsf(xr[o]), 0.01f, 1.0f);
    }

#pragma unroll
    for (int step = 0; step < 5; step++) {
        float Sd = 0.f, Cd = 0.f, St = 0.f, Ct = 0.f, Sg = 0.f, Cg = 0.f;
#pragma unroll
        for (int k = 0; k < NPER; k++) {
            if (k < 2)      { Sd += s[k]; Cd += c[k]; }
            else if (k < 6) { St += s[k]; Ct += c[k]; }
            else            { Sg += s[k]; Cg += c[k]; }
        }
        Sd = warp_sum(Sd); Cd = warp_sum(Cd);
        St = warp_sum(St); Ct = warp_sum(Ct);
        Sg = warp_sum(Sg); Cg = warp_sum(Cg);

        const float mSd = Sd * (1.0f / 64.0f),  mCd = Cd * (1.0f / 64.0f);
        const float mSt = St * (1.0f / 128.0f), mCt = Ct * (1.0f / 128.0f);
        const float mSg = Sg * (1.0f / 512.0f), mCg = Cg * (1.0f / 512.0f);

        // cos(circular mean phase) of delta / theta bands
        const float cpd = mCd * rsqrtf(fmaf(mSd, mSd, mCd * mCd));
        const float cpt = mCt * rsqrtf(fmaf(mSt, mSt, mCt * mCt));
        const float fT = fmaf(0.003f, cpd, 1.0f);  // DT * PAC_DT = 0.003
        const float fG = fmaf(0.003f, cpt, 1.0f);

        // dt * COUPLING = 0.02
        const float kSd = 0.02f * mSd, kCd = 0.02f * mCd;
        const float kSt = 0.02f * mSt, kCt = 0.02f * mCt;
        const float kSg = 0.02f * mSg, kCg = 0.02f * mCg;

#pragma unroll
        for (int k = 0; k < NPER; k++) {
            float kS, kC, af;
            if (k < 2)      { kS = kSd; kC = kCd; af = 1.0f; }
            else if (k < 6) { kS = kSt; kC = kCt; af = fT;   }
            else            { kS = kSg; kC = kCg; af = fG;   }
            // small Kuramoto rotation angle
            const float al = fmaf(kS, c[k], -kC * s[k]);
            const float t2 = al * al;
            const float sc = al * fmaf(t2, -0.16666667f, 1.0f);
            const float cc = fmaf(t2, -0.5f, 1.0f);
            const float c1 = fmaf(c[k], cc, -s[k] * sc);
            const float s1 = fmaf(s[k], cc,  c[k] * sc);
            const float2 w = w0[k * 32 + lane];  // constant rotation
            c[k] = fmaf(c1, w.x, -s1 * w.y);
            s[k] = fmaf(s1, w.x,  c1 * w.y);
            a[k] *= af;
        }
    }

    // raw rates
    float r[NPER];
    float mx = 0.0f;
#pragma unroll
    for (int k = 0; k < NPER; k++) {
        r[k] = a[k] * fmaf(0.5f, c[k], 0.5f);
        mx = fmaxf(mx, r[k]);
    }
#pragma unroll
    for (int off = 16; off; off >>= 1)
        mx = fmaxf(mx, __shfl_xor_sync(0xffffffffu, mx, off));

    // Bisection for ascending order stats v[632] (72nd largest) and v[633]
    // (71st largest). Both searches fused: counts packed low/high 16 bits,
    // single shfl-reduce chain per iteration. 24 iters -> residual ~1e-7.
    float lo1 = 0.0f, hi1 = mx + 1e-3f;  // -> v[633]
    float lo2 = 0.0f, hi2 = hi1;         // -> v[632]
    for (int it = 0; it < 24; it++) {
        const float m1 = 0.5f * (lo1 + hi1);
        const float m2 = 0.5f * (lo2 + hi2);
        int cnt = 0;
#pragma unroll
        for (int k = 0; k < NPER; k++) {
            cnt += (r[k] > m1) ? 1 : 0;
            cnt += (r[k] > m2) ? 0x10000 : 0;
        }
#pragma unroll
        for (int off = 16; off; off >>= 1)
            cnt += __shfl_xor_sync(0xffffffffu, cnt, off);
        if ((cnt & 0xffff) >= 71) lo1 = m1; else hi1 = m1;
        if ((cnt >> 16)    >= 72) lo2 = m2; else hi2 = m2;
    }
    const float v71 = 0.5f * (lo1 + hi1);  // v[633]
    const float v72 = 0.5f * (lo2 + hi2);  // v[632]
    const float thr = fmaf(0.7f, v71 - v72, v72);  // quantile interpolation

    float* rr = g_rate + (size_t)sample * NOSC;
#pragma unroll
    for (int k = 0; k < NPER; k++) {
        const float z = (r[k] - thr) * 10.0f;
        const float sig = __fdividef(1.0f, 1.0f + __expf(-z));
        rr[k * 32 + lane] = r[k] * sig;
    }
}

// ---------------------------------------------------------------------------
// Kernel 2: out = rate @ W^T + b   (fp32, packed f32x2 FFMA2)
// Tiles: 128M x 128N x 16K, 256 threads, 8Mx8N per thread (M packed in pairs).
// Single barrier per K-chunk: reads of the buffer being overwritten completed
// before the barrier that closed the previous iteration.
// ---------------------------------------------------------------------------
#define BM 128
#define BN 128
#define BK 16

__global__ __launch_bounds__(256, 2) void gemm_kernel(const float* __restrict__ W,
                                                      const float* __restrict__ bias,
                                                      float* __restrict__ out) {
    __shared__ __align__(16) float As[2][BK][BM];
    __shared__ __align__(16) float Bs[2][BK][BN];

    const int t = threadIdx.x;
    const int n0 = blockIdx.x * BN;
    const int m0 = blockIdx.y * BM;
    const int lr = t >> 2;          // 0..63: row within half-tile
    const int lc = (t & 3) * 4;     // k element group start
    const float* A = g_rate;

    const int nr0 = n0 + lr, nr1 = n0 + lr + 64;

    float4 ra0, ra1, rb0, rb1;
    auto ldg = [&](int kc) {
        const int kbase = kc * BK + lc;
        ra0 = *(const float4*)(A + (size_t)(m0 + lr) * KDIM + kbase);
        ra1 = *(const float4*)(A + (size_t)(m0 + lr + 64) * KDIM + kbase);
        rb0 = (nr0 < NCLS) ? *(const float4*)(W + (size_t)nr0 * KDIM + kbase)
                           : make_float4(0.f, 0.f, 0.f, 0.f);
        rb1 = (nr1 < NCLS) ? *(const float4*)(W + (size_t)nr1 * KDIM + kbase)
                           : make_float4(0.f, 0.f, 0.f, 0.f);
    };
    auto sts = [&](int buf) {
        As[buf][lc + 0][lr] = ra0.x; As[buf][lc + 1][lr] = ra0.y;
        As[buf][lc + 2][lr] = ra0.z; As[buf][lc + 3][lr] = ra0.w;
        As[buf][lc + 0][lr + 64] = ra1.x; As[buf][lc + 1][lr + 64] = ra1.y;
        As[buf][lc + 2][lr + 64] = ra1.z; As[buf][lc + 3][lr + 64] = ra1.w;
        Bs[buf][lc + 0][lr] = rb0.x; Bs[buf][lc + 1][lr] = rb0.y;
        Bs[buf][lc + 2][lr] = rb0.z; Bs[buf][lc + 3][lr] = rb0.w;
        Bs[buf][lc + 0][lr + 64] = rb1.x; Bs[buf][lc + 1][lr + 64] = rb1.y;
        Bs[buf][lc + 2][lr + 64] = rb1.z; Bs[buf][lc + 3][lr + 64] = rb1.w;
    };

    const int tn = (t & 15) * 8;
    const int tm = (t >> 4) * 8;

    unsigned long long acc[4][8];
#pragma unroll
    for (int p = 0; p < 4; p++)
#pragma unroll
        for (int j = 0; j < 8; j++) acc[p][j] = 0ull;

    ldg(0);
    sts(0);
    __syncthreads();

    for (int kc = 0; kc < KDIM / BK; kc++) {
        const int buf = kc & 1;
        if (kc < KDIM / BK - 1) ldg(kc + 1);
#pragma unroll
        for (int kk = 0; kk < BK; kk++) {
            unsigned long long av[4];
#pragma unroll
            for (int p = 0; p < 4; p++)
                av[p] = *(const unsigned long long*)&As[buf][kk][tm + 2 * p];
            const float4 b0 = *(const float4*)&Bs[buf][kk][tn];
            const float4 b1 = *(const float4*)&Bs[buf][kk][tn + 4];
            unsigned long long bv[8];
            bv[0] = dup2(b0.x); bv[1] = dup2(b0.y); bv[2] = dup2(b0.z); bv[3] = dup2(b0.w);
            bv[4] = dup2(b1.x); bv[5] = dup2(b1.y); bv[6] = dup2(b1.z); bv[7] = dup2(b1.w);
#pragma unroll
            for (int p = 0; p < 4; p++)
#pragma unroll
                for (int j = 0; j < 8; j++) ffma2(acc[p][j], av[p], bv[j]);
        }
        if (kc < KDIM / BK - 1) {
            sts(1 - buf);          // WAR-safe: see header comment
            __syncthreads();
        }
    }

    // epilogue: + bias, store
    float bv[8];
#pragma unroll
    for (int j = 0; j < 8; j++) {
        const int n = n0 + tn + j;
        bv[j] = (n < NCLS) ? bias[n] : 0.0f;
    }
#pragma unroll
    for (int p = 0; p < 4; p++) {
        float2 f[8];
#pragma unroll
        for (int j = 0; j < 8; j++) f[j] = unpk(acc[p][j]);
#pragma unroll
        for (int h = 0; h < 2; h++) {
            const int row = m0 + tm + 2 * p + h;
            float v[8];
#pragma unroll
            for (int j = 0; j < 8; j++)
                v[j] = ((h == 0) ? f[j].x : f[j].y) + bv[j];
            float* op = out + (size_t)row * NCLS + n0 + tn;
            if (n0 + tn + 7 < NCLS) {
                *(float4*)(op)     = make_float4(v[0], v[1], v[2], v[3]);
                *(float4*)(op + 4) = make_float4(v[4], v[5], v[6], v[7]);
            } else {
#pragma unroll
                for (int j = 0; j < 8; j++)
                    if (n0 + tn + j < NCLS) op[j] = v[j];
            }
        }
    }
}

// ---------------------------------------------------------------------------
// Launch
// ---------------------------------------------------------------------------
extern "C" void kernel_launch(void* const* d_in, const int* in_sizes, int n_in,
                              void* d_out, int out_size) {
    const float* x  = (const float*)d_in[0];   // (65536, 704)
    const float* p0 = (const float*)d_in[1];   // (65536, 704)
    const float* W  = (const float*)d_in[2];   // (1000, 704)
    const float* b  = (const float*)d_in[3];   // (1000,)
    float* out = (float*)d_out;                // (65536, 1000)

    dyn_kernel<<<NSAMP / 8, 256>>>(x, p0);
    gemm_kernel<<<dim3((NCLS + BN - 1) / BN, NSAMP / BM), 256>>>(W, b, out);
}

// round 7
// speedup vs baseline: 1.9279x; 1.9279x over previous
#include <cuda_runtime.h>
#include <cuda_bf16.h>
#include <cstdint>

// ---------------------------------------------------------------------------
// Problem constants
// ---------------------------------------------------------------------------
#define NOSC 704          // 64 delta + 128 theta + 512 gamma
#define NPER 22           // oscillators per lane (704 / 32)
#define NCLS 1000
#define KDIM 704
#define NSAMP 65536
#define NPAD 1024         // class rows padded to tile multiple

// ---------------------------------------------------------------------------
// Scratch (static __device__ arrays = sanctioned no-alloc scratch)
// rate and W split into bf16 hi/lo pairs for 3-product split GEMM:
//   a*b ~= ah*bh + ah*bl + al*bh   (error ~2^-17 relative)
// ---------------------------------------------------------------------------
__device__ __nv_bfloat16 g_rate_hi[(size_t)NSAMP * KDIM];
__device__ __nv_bfloat16 g_rate_lo[(size_t)NSAMP * KDIM];
__device__ __nv_bfloat16 g_W_hi[(size_t)NPAD * KDIM];
__device__ __nv_bfloat16 g_W_lo[(size_t)NPAD * KDIM];

// ---------------------------------------------------------------------------
// Family-common PTX helpers (all legal for target sm_103, no 'a' suffix)
// ---------------------------------------------------------------------------
__device__ __forceinline__ uint32_t smem_u32(const void* p) {
    uint32_t a;
    asm("{ .reg .u64 t; cvta.to.shared.u64 t, %1; cvt.u32.u64 %0, t; }"
        : "=r"(a) : "l"(p));
    return a;
}

__device__ __forceinline__ void cp16(uint32_t s, const void* g) {
    asm volatile("cp.async.cg.shared.global [%0], [%1], 16;" :: "r"(s), "l"(g));
}
#define CP_COMMIT() asm volatile("cp.async.commit_group;" ::: "memory")

__device__ __forceinline__ void ldsm4(uint32_t* r, uint32_t addr) {
    asm volatile("ldmatrix.sync.aligned.m8n8.x4.shared.b16 {%0,%1,%2,%3}, [%4];"
                 : "=r"(r[0]), "=r"(r[1]), "=r"(r[2]), "=r"(r[3]) : "r"(addr));
}

__device__ __forceinline__ void mma16816(float* c, const uint32_t* a,
                                         const uint32_t* b) {
    asm volatile(
        "mma.sync.aligned.m16n8k16.row.col.f32.bf16.bf16.f32 "
        "{%0,%1,%2,%3}, {%4,%5,%6,%7}, {%8,%9}, {%0,%1,%2,%3};"
        : "+f"(c[0]), "+f"(c[1]), "+f"(c[2]), "+f"(c[3])
        : "r"(a[0]), "r"(a[1]), "r"(a[2]), "r"(a[3]), "r"(b[0]), "r"(b[1]));
}

// ---------------------------------------------------------------------------
// Kernel 0: split W (1000x704 f32) -> bf16 hi/lo, zero-padded to 1024 rows
// ---------------------------------------------------------------------------
__global__ void wconv_kernel(const float* __restrict__ W) {
    const int i = blockIdx.x * 256 + threadIdx.x;  // over NPAD*KDIM, exact grid
    const int row = i / KDIM;
    const int col = i - row * KDIM;
    float v = (row < NCLS) ? W[row * KDIM + col] : 0.0f;
    const __nv_bfloat16 h = __float2bfloat16(v);
    const float rem = v - __bfloat162float(h);
    g_W_hi[i] = h;
    g_W_lo[i] = __float2bfloat16(rem);
}

// ---------------------------------------------------------------------------
// Kernel 1: oscillator dynamics + soft top-10% gate -> rate hi/lo (bf16)
// (math identical to the 2546us passing baseline)
// ---------------------------------------------------------------------------
__device__ __forceinline__ float warp_sum(float v) {
#pragma unroll
    for (int off = 16; off; off >>= 1) v += __shfl_xor_sync(0xffffffffu, v, off);
    return v;
}

__global__ __launch_bounds__(256, 2) void dyn_kernel(const float* __restrict__ x,
                                                     const float* __restrict__ p0) {
    __shared__ float2 w0[NOSC];  // (cos, sin) of dt*2*pi*f per oscillator

    const int t = threadIdx.x;
    for (int i = t; i < NOSC; i += 256) {
        float f;
        if (i < 64)       f = 1.0f  + 3.0f  * (float)i         * (1.0f / 63.0f);
        else if (i < 192) f = 4.0f  + 4.0f  * (float)(i - 64)  * (1.0f / 127.0f);
        else              f = 30.0f + 50.0f * (float)(i - 192) * (1.0f / 511.0f);
        const float a0 = 0.01f * (6.283185307179586f * f);
        float sn, cs;
        sincosf(a0, &sn, &cs);
        w0[i] = make_float2(cs, sn);
    }
    __syncthreads();

    const int lane = t & 31;
    const int warp = t >> 5;
    const int sample = blockIdx.x * 8 + warp;
    const float* xr = x  + (size_t)sample * NOSC;
    const float* pr = p0 + (size_t)sample * NOSC;

    float c[NPER], s[NPER], a[NPER];
#pragma unroll
    for (int k = 0; k < NPER; k++) {
        const int o = k * 32 + lane;
        const float ph = pr[o] * 6.2831853071795864f;
        __sincosf(ph, &s[k], &c[k]);
        a[k] = fmaf(fabsf(xr[o]), 0.01f, 1.0f);
    }

#pragma unroll
    for (int step = 0; step < 5; step++) {
        float Sd = 0.f, Cd = 0.f, St = 0.f, Ct = 0.f, Sg = 0.f, Cg = 0.f;
#pragma unroll
        for (int k = 0; k < NPER; k++) {
            if (k < 2)      { Sd += s[k]; Cd += c[k]; }
            else if (k < 6) { St += s[k]; Ct += c[k]; }
            else            { Sg += s[k]; Cg += c[k]; }
        }
        Sd = warp_sum(Sd); Cd = warp_sum(Cd);
        St = warp_sum(St); Ct = warp_sum(Ct);
        Sg = warp_sum(Sg); Cg = warp_sum(Cg);

        const float mSd = Sd * (1.0f / 64.0f),  mCd = Cd * (1.0f / 64.0f);
        const float mSt = St * (1.0f / 128.0f), mCt = Ct * (1.0f / 128.0f);
        const float mSg = Sg * (1.0f / 512.0f), mCg = Cg * (1.0f / 512.0f);

        const float cpd = mCd * rsqrtf(fmaf(mSd, mSd, mCd * mCd));
        const float cpt = mCt * rsqrtf(fmaf(mSt, mSt, mCt * mCt));
        const float fT = fmaf(0.003f, cpd, 1.0f);  // DT * PAC_DT
        const float fG = fmaf(0.003f, cpt, 1.0f);

        const float kSd = 0.02f * mSd, kCd = 0.02f * mCd;  // dt * K
        const float kSt = 0.02f * mSt, kCt = 0.02f * mCt;
        const float kSg = 0.02f * mSg, kCg = 0.02f * mCg;

#pragma unroll
        for (int k = 0; k < NPER; k++) {
            float kS, kC, af;
            if (k < 2)      { kS = kSd; kC = kCd; af = 1.0f; }
            else if (k < 6) { kS = kSt; kC = kCt; af = fT;   }
            else            { kS = kSg; kC = kCg; af = fG;   }
            const float al = fmaf(kS, c[k], -kC * s[k]);
            const float t2 = al * al;
            const float sc = al * fmaf(t2, -0.16666667f, 1.0f);
            const float cc = fmaf(t2, -0.5f, 1.0f);
            const float c1 = fmaf(c[k], cc, -s[k] * sc);
            const float s1 = fmaf(s[k], cc,  c[k] * sc);
            const float2 w = w0[k * 32 + lane];
            c[k] = fmaf(c1, w.x, -s1 * w.y);
            s[k] = fmaf(s1, w.x,  c1 * w.y);
            a[k] *= af;
        }
    }

    float r[NPER];
    float mx = 0.0f;
#pragma unroll
    for (int k = 0; k < NPER; k++) {
        r[k] = a[k] * fmaf(0.5f, c[k], 0.5f);
        mx = fmaxf(mx, r[k]);
    }
#pragma unroll
    for (int off = 16; off; off >>= 1)
        mx = fmaxf(mx, __shfl_xor_sync(0xffffffffu, mx, off));

    // Dual-rank bisection for ascending order stats v[632] / v[633]
    float lo1 = 0.0f, hi1 = mx + 1e-3f;  // -> v[633]
    float lo2 = 0.0f, hi2 = hi1;         // -> v[632]
    for (int it = 0; it < 24; it++) {
        const float m1 = 0.5f * (lo1 + hi1);
        const float m2 = 0.5f * (lo2 + hi2);
        int cnt = 0;
#pragma unroll
        for (int k = 0; k < NPER; k++) {
            cnt += (r[k] > m1) ? 1 : 0;
            cnt += (r[k] > m2) ? 0x10000 : 0;
        }
#pragma unroll
        for (int off = 16; off; off >>= 1)
            cnt += __shfl_xor_sync(0xffffffffu, cnt, off);
        if ((cnt & 0xffff) >= 71) lo1 = m1; else hi1 = m1;
        if ((cnt >> 16)    >= 72) lo2 = m2; else hi2 = m2;
    }
    const float v71 = 0.5f * (lo1 + hi1);
    const float v72 = 0.5f * (lo2 + hi2);
    const float thr = fmaf(0.7f, v71 - v72, v72);

    __nv_bfloat16* rh = g_rate_hi + (size_t)sample * NOSC;
    __nv_bfloat16* rl = g_rate_lo + (size_t)sample * NOSC;
#pragma unroll
    for (int k = 0; k < NPER; k++) {
        const float z = (r[k] - thr) * 10.0f;
        const float sig = __fdividef(1.0f, 1.0f + __expf(-z));
        const float v = r[k] * sig;
        const __nv_bfloat16 h = __float2bfloat16(v);
        const float rem = v - __bfloat162float(h);
        rh[k * 32 + lane] = h;
        rl[k * 32 + lane] = __float2bfloat16(rem);
    }
}

// ---------------------------------------------------------------------------
// Kernel 2: bf16 split GEMM via family-common mma.sync (legacy tensor path).
// CTA tile 128M x 128N, BK=64 (11 chunks). 8 warps = 2(M) x 4(N), each warp
// 64x32 via m16n8k16 frags. Smem rows padded to 144B: 16B-aligned and the
// 8 ldmatrix row addresses land in 8 distinct banks (stride = 4 banks mod 32).
// cp.async double-buffered; one commit group per chunk.
// ---------------------------------------------------------------------------
#define BM 128
#define BN 128
#define BKC 64
#define NCH (KDIM / BKC)       // 11
#define RSB 144                 // smem row stride bytes (128B data + 16 pad)
#define TILE_B (128 * RSB)      // 18432 B
#define BUF_B  (4 * TILE_B)     // Ah, Al, Bh, Bl = 73728 B
#define GEMM_SMEM (2 * BUF_B)   // 147456 B

__global__ __launch_bounds__(256, 1) void gemm_kernel(const float* __restrict__ bias,
                                                      float* __restrict__ out) {
    extern __shared__ char smem[];
    const uint32_t sb = smem_u32(smem);
    const int t = threadIdx.x;
    const int wid = t >> 5;
    const int lane = t & 31;
    const int n0 = blockIdx.x * BN;
    const int m0 = blockIdx.y * BM;
    const int wm = (wid & 1) * 64;   // warp M offset
    const int wn = (wid >> 1) * 32;  // warp N offset

    const __nv_bfloat16* Ah = g_rate_hi + (size_t)m0 * KDIM;
    const __nv_bfloat16* Al = g_rate_lo + (size_t)m0 * KDIM;
    const __nv_bfloat16* Bh = g_W_hi + (size_t)n0 * KDIM;
    const __nv_bfloat16* Bl = g_W_lo + (size_t)n0 * KDIM;

    // per-chunk async load: 4 tiles x 128 rows x 8 segs(16B) = 4096 cp.async/CTA
    auto issue = [&](int kc) {
        const uint32_t bb = sb + (kc & 1) * BUF_B;
        const int kb = kc * BKC;
#pragma unroll
        for (int i = 0; i < 4; i++) {
            const int u = i * 256 + t;          // 0..1023
            const int row = u >> 3, seg = u & 7;
            const uint32_t so = row * RSB + seg * 16;
            const size_t go = (size_t)row * KDIM + kb + seg * 8;
            cp16(bb + so,              Ah + go);
            cp16(bb + TILE_B + so,     Al + go);
            cp16(bb + 2 * TILE_B + so, Bh + go);
            cp16(bb + 3 * TILE_B + so, Bl + go);
        }
        CP_COMMIT();
    };

    float acc[4][4][4];
#pragma unroll
    for (int mf = 0; mf < 4; mf++)
#pragma unroll
        for (int nf = 0; nf < 4; nf++)
#pragma unroll
            for (int e = 0; e < 4; e++) acc[mf][nf][e] = 0.0f;

    issue(0);

    for (int kc = 0; kc < NCH; kc++) {
        if (kc < NCH - 1) {
            issue(kc + 1);
            asm volatile("cp.async.wait_group 1;" ::: "memory");
        } else {
            asm volatile("cp.async.wait_group 0;" ::: "memory");
        }
        __syncthreads();

        const uint32_t base = sb + (kc & 1) * BUF_B;
#pragma unroll
        for (int ks = 0; ks < 4; ks++) {
            uint32_t ah[4][4], al[4][4], bh[4][2], bl[4][2];
            // A frags: lanes 0-15 -> rows, lane>>4 selects k-half (16B)
#pragma unroll
            for (int mf = 0; mf < 4; mf++) {
                const uint32_t ad = base + (wm + mf * 16 + (lane & 15)) * RSB +
                                    (lane >> 4) * 16 + ks * 32;
                ldsm4(ah[mf], ad);
                ldsm4(al[mf], ad + TILE_B);
            }
            // B frags: n = wn + nh*16 + ((lane>>4)<<3) + (lane&7),
            //          k-half = (lane>>3)&1
#pragma unroll
            for (int nh = 0; nh < 2; nh++) {
                const uint32_t bd = base + 2 * TILE_B +
                                    (wn + nh * 16 + ((lane >> 4) << 3) + (lane & 7)) * RSB +
                                    ((lane >> 3) & 1) * 16 + ks * 32;
                uint32_t r[4];
                ldsm4(r, bd);
                bh[nh * 2][0] = r[0]; bh[nh * 2][1] = r[1];
                bh[nh * 2 + 1][0] = r[2]; bh[nh * 2 + 1][1] = r[3];
                ldsm4(r, bd + TILE_B);
                bl[nh * 2][0] = r[0]; bl[nh * 2][1] = r[1];
                bl[nh * 2 + 1][0] = r[2]; bl[nh * 2 + 1][1] = r[3];
            }
#pragma unroll
            for (int mf = 0; mf < 4; mf++)
#pragma unroll
                for (int nf = 0; nf < 4; nf++) {
                    mma16816(acc[mf][nf], ah[mf], bh[nf]);
                    mma16816(acc[mf][nf], ah[mf], bl[nf]);
                    mma16816(acc[mf][nf], al[mf], bh[nf]);
                }
        }
        __syncthreads();
    }

    // epilogue: +bias, direct v2 stores (4-lane groups cover 32B contiguous)
#pragma unroll
    for (int nf = 0; nf < 4; nf++) {
        const int nbase = n0 + wn + nf * 8;       // NCLS = 1000 = 125*8
        if (nbase >= NCLS) continue;
        const int col = nbase + (lane & 3) * 2;
        const float b0 = bias[col], b1 = bias[col + 1];
#pragma unroll
        for (int mf = 0; mf < 4; mf++) {
            const int row = m0 + wm + mf * 16 + (lane >> 2);
            float2 v0 = make_float2(acc[mf][nf][0] + b0, acc[mf][nf][1] + b1);
            float2 v1 = make_float2(acc[mf][nf][2] + b0, acc[mf][nf][3] + b1);
            *(float2*)(out + (size_t)row * NCLS + col) = v0;
            *(float2*)(out + (size_t)(row + 8) * NCLS + col) = v1;
        }
    }
}

// ---------------------------------------------------------------------------
// Launch
// ---------------------------------------------------------------------------
extern "C" void kernel_launch(void* const* d_in, const int* in_sizes, int n_in,
                              void* d_out, int out_size) {
    const float* x  = (const float*)d_in[0];   // (65536, 704)
    const float* p0 = (const float*)d_in[1];   // (65536, 704)
    const float* W  = (const float*)d_in[2];   // (1000, 704)
    const float* b  = (const float*)d_in[3];   // (1000,)
    float* out = (float*)d_out;                // (65536, 1000)

    cudaFuncSetAttribute(gemm_kernel, cudaFuncAttributeMaxDynamicSharedMemorySize,
                         GEMM_SMEM);

    wconv_kernel<<<(NPAD * KDIM) / 256, 256>>>(W);
    dyn_kernel<<<NSAMP / 8, 256>>>(x, p0);
    gemm_kernel<<<dim3(NPAD / BN, NSAMP / BM), 256, GEMM_SMEM>>>(b, out);
}

// round 13
// speedup vs baseline: 1.9824x; 1.0283x over previous
#include <cuda_runtime.h>
#include <cuda_bf16.h>
#include <cstdint>

// ---------------------------------------------------------------------------
// Problem constants
// ---------------------------------------------------------------------------
#define NOSC 704          // 64 delta + 128 theta + 512 gamma
#define NPER 22           // oscillators per lane (704 / 32)
#define NPAIR 11          // f32x2-packed oscillator pairs per lane
#define NCLS 1000
#define KDIM 704
#define NSAMP 65536
#define NPAD 1024         // class rows padded to tile multiple

typedef unsigned long long ull;

// ---------------------------------------------------------------------------
// Scratch (static __device__ arrays = sanctioned no-alloc scratch)
// rate and W split into bf16 hi/lo pairs for 3-product split GEMM:
//   a*b ~= ah*bh + ah*bl + al*bh   (error ~2^-17 relative)
// ---------------------------------------------------------------------------
__device__ __nv_bfloat16 g_rate_hi[(size_t)NSAMP * KDIM];
__device__ __nv_bfloat16 g_rate_lo[(size_t)NSAMP * KDIM];
__device__ __nv_bfloat16 g_W_hi[(size_t)NPAD * KDIM];
__device__ __nv_bfloat16 g_W_lo[(size_t)NPAD * KDIM];

// ---------------------------------------------------------------------------
// Family-common PTX helpers (all legal for target sm_103, no 'a' suffix)
// ---------------------------------------------------------------------------
__device__ __forceinline__ uint32_t smem_u32(const void* p) {
    uint32_t a;
    asm("{ .reg .u64 t; cvta.to.shared.u64 t, %1; cvt.u32.u64 %0, t; }"
        : "=r"(a) : "l"(p));
    return a;
}

__device__ __forceinline__ void cp16(uint32_t s, const void* g) {
    asm volatile("cp.async.cg.shared.global [%0], [%1], 16;" :: "r"(s), "l"(g));
}
#define CP_COMMIT() asm volatile("cp.async.commit_group;" ::: "memory")

__device__ __forceinline__ void ldsm4(uint32_t* r, uint32_t addr) {
    asm volatile("ldmatrix.sync.aligned.m8n8.x4.shared.b16 {%0,%1,%2,%3}, [%4];"
                 : "=r"(r[0]), "=r"(r[1]), "=r"(r[2]), "=r"(r[3]) : "r"(addr));
}

__device__ __forceinline__ void mma16816(float* c, const uint32_t* a,
                                         const uint32_t* b) {
    asm volatile(
        "mma.sync.aligned.m16n8k16.row.col.f32.bf16.bf16.f32 "
        "{%0,%1,%2,%3}, {%4,%5,%6,%7}, {%8,%9}, {%0,%1,%2,%3};"
        : "+f"(c[0]), "+f"(c[1]), "+f"(c[2]), "+f"(c[3])
        : "r"(a[0]), "r"(a[1]), "r"(a[2]), "r"(a[3]), "r"(b[0]), "r"(b[1]));
}

// packed f32x2 ops (only fma.rn.f32x2 + mov.b64 — both proven on this build)
__device__ __forceinline__ ull f2(ull a, ull b, ull c) {
    ull d;
    asm("fma.rn.f32x2 %0, %1, %2, %3;" : "=l"(d) : "l"(a), "l"(b), "l"(c));
    return d;
}
__device__ __forceinline__ ull pk2(float lo, float hi) {
    ull r;
    asm("mov.b64 %0, {%1, %2};" : "=l"(r) : "f"(lo), "f"(hi));
    return r;
}
__device__ __forceinline__ float2 up2(ull v) {
    float lo, hi;
    asm("mov.b64 {%0, %1}, %2;" : "=f"(lo), "=f"(hi) : "l"(v));
    return make_float2(lo, hi);
}
__device__ __forceinline__ ull dup2(float v) { return pk2(v, v); }

__device__ __forceinline__ float warp_sum(float v) {
#pragma unroll
    for (int off = 16; off; off >>= 1) v += __shfl_xor_sync(0xffffffffu, v, off);
    return v;
}

// ---------------------------------------------------------------------------
// Kernel 1: oscillator dynamics + soft top-10% gate -> rate hi/lo (bf16).
// State packed as f32x2 pairs (oscillators 2p, 2p+1 — each pair is
// band-homogeneous since bands split at k=2 and k=6). Arithmetic per fp32
// lane identical to the validated scalar version.
// Also folds the W hi/lo split (88 elements per block) so the launch stream
// is [dyn, gemm] only.
// ---------------------------------------------------------------------------
__global__ __launch_bounds__(256, 2) void dyn_kernel(const float* __restrict__ x,
                                                     const float* __restrict__ p0,
                                                     const float* __restrict__ W) {
    // packed rotation constants: pair p, lane l -> floats at [p*64 + 2l + slot]
    // __align__(16): read with 64-bit LDS — base must be 8B-aligned.
    __shared__ __align__(16) float wxs[NOSC];
    __shared__ __align__(16) float wys[NOSC];
    __shared__ __align__(16) float nwys[NOSC];

    const int t = threadIdx.x;
    const int bid = blockIdx.x;

    // folded W conversion: 8192 blocks x 88 = 1024*704 exactly
    if (t < 88) {
        const int i = bid * 88 + t;
        const int row = i / KDIM;
        const int col = i - row * KDIM;
        const float v = (row < NCLS) ? W[row * KDIM + col] : 0.0f;
        const __nv_bfloat16 h = __float2bfloat16(v);
        g_W_hi[i] = h;
        g_W_lo[i] = __float2bfloat16(v - __bfloat162float(h));
    }

    for (int o = t; o < NOSC; o += 256) {
        float f;
        if (o < 64)       f = 1.0f  + 3.0f  * (float)o         * (1.0f / 63.0f);
        else if (o < 192) f = 4.0f  + 4.0f  * (float)(o - 64)  * (1.0f / 127.0f);
        else              f = 30.0f + 50.0f * (float)(o - 192) * (1.0f / 511.0f);
        const float a0 = 0.01f * (6.283185307179586f * f);
        float sn, cs;
        sincosf(a0, &sn, &cs);
        const int k = o >> 5, lane_ = o & 31;
        const int idx = (k >> 1) * 64 + lane_ * 2 + (k & 1);
        wxs[idx] = cs;
        wys[idx] = sn;
        nwys[idx] = -sn;
    }
    __syncthreads();

    const int lane = t & 31;
    const int warp = t >> 5;
    const int sample = bid * 8 + warp;
    const float* xr = x  + (size_t)sample * NOSC;
    const float* pr = p0 + (size_t)sample * NOSC;

    ull c2[NPAIR], s2[NPAIR], a2[NPAIR];
#pragma unroll
    for (int p = 0; p < NPAIR; p++) {
        const int o0 = (2 * p) * 32 + lane, o1 = o0 + 32;
        float s0, c0, s1, c1;
        __sincosf(pr[o0] * 6.2831853071795864f, &s0, &c0);
        __sincosf(pr[o1] * 6.2831853071795864f, &s1, &c1);
        c2[p] = pk2(c0, c1);
        s2[p] = pk2(s0, s1);
        a2[p] = pk2(fmaf(fabsf(xr[o0]), 0.01f, 1.0f),
                    fmaf(fabsf(xr[o1]), 0.01f, 1.0f));
    }

    const ull one2 = dup2(1.0f), zero2 = dup2(0.0f);
    const ull c6n2 = dup2(-0.16666667f), ch2 = dup2(-0.5f), mneg2 = dup2(-1.0f);
    const ull half2 = dup2(0.5f);

#pragma unroll
    for (int step = 0; step < 5; step++) {
        // band sums (packed accumulate, unpack once per band)
        ull Sd2 = s2[0], Cd2 = c2[0];
        ull St2 = f2(one2, s2[1], s2[2]), Ct2 = f2(one2, c2[1], c2[2]);
        ull Sg2 = s2[3], Cg2 = c2[3];
#pragma unroll
        for (int p = 4; p < NPAIR; p++) {
            Sg2 = f2(one2, s2[p], Sg2);
            Cg2 = f2(one2, c2[p], Cg2);
        }
        float2 q;
        q = up2(Sd2); float Sd = q.x + q.y;
        q = up2(Cd2); float Cd = q.x + q.y;
        q = up2(St2); float St = q.x + q.y;
        q = up2(Ct2); float Ct = q.x + q.y;
        q = up2(Sg2); float Sg = q.x + q.y;
        q = up2(Cg2); float Cg = q.x + q.y;
        Sd = warp_sum(Sd); Cd = warp_sum(Cd);
        St = warp_sum(St); Ct = warp_sum(Ct);
        Sg = warp_sum(Sg); Cg = warp_sum(Cg);

        const float mSd = Sd * (1.0f / 64.0f),  mCd = Cd * (1.0f / 64.0f);
        const float mSt = St * (1.0f / 128.0f), mCt = Ct * (1.0f / 128.0f);
        const float mSg = Sg * (1.0f / 512.0f), mCg = Cg * (1.0f / 512.0f);

        const float cpd = mCd * rsqrtf(fmaf(mSd, mSd, mCd * mCd));
        const float cpt = mCt * rsqrtf(fmaf(mSt, mSt, mCt * mCt));

        // per-band packed constants
        const ull kS_d = dup2(0.02f * mSd), nkC_d = dup2(-0.02f * mCd);
        const ull kS_t = dup2(0.02f * mSt), nkC_t = dup2(-0.02f * mCt);
        const ull kS_g = dup2(0.02f * mSg), nkC_g = dup2(-0.02f * mCg);
        const ull af_t = dup2(fmaf(0.003f, cpd, 1.0f));
        const ull af_g = dup2(fmaf(0.003f, cpt, 1.0f));

#pragma unroll
        for (int p = 0; p < NPAIR; p++) {
            ull kS, nkC, af;
            if (p == 0)      { kS = kS_d; nkC = nkC_d; af = one2; }
            else if (p < 3)  { kS = kS_t; nkC = nkC_t; af = af_t; }
            else             { kS = kS_g; nkC = nkC_g; af = af_g; }
            const ull s_ = s2[p], c_ = c2[p];
            const ull al = f2(kS, c_, f2(nkC, s_, zero2));       // small angle
            const ull tq = f2(al, al, zero2);
            const ull sc = f2(al, f2(tq, c6n2, one2), zero2);
            const ull cc = f2(tq, ch2, one2);
            const ull ns = f2(s_, mneg2, zero2);
            const ull c1 = f2(ns, sc, f2(c_, cc, zero2));        // c*cc - s*sc
            const ull s1 = f2(c_, sc, f2(s_, cc, zero2));        // s*cc + c*sc
            const ull wx  = *(const ull*)(wxs  + p * 64 + lane * 2);
            const ull wy  = *(const ull*)(wys  + p * 64 + lane * 2);
            const ull nwy = *(const ull*)(nwys + p * 64 + lane * 2);
            c2[p] = f2(s1, nwy, f2(c1, wx, zero2));              // constant rot
            s2[p] = f2(c1, wy,  f2(s1, wx, zero2));
            a2[p] = f2(a2[p], af, zero2);
        }
    }

    // raw rates (unpack to scalars for max/bisection/output)
    float r[NPER];
    float mx = 0.0f;
#pragma unroll
    for (int p = 0; p < NPAIR; p++) {
        const ull rr = f2(a2[p], f2(c2[p], half2, half2), zero2);
        const float2 q = up2(rr);
        r[2 * p] = q.x;
        r[2 * p + 1] = q.y;
        mx = fmaxf(mx, fmaxf(q.x, q.y));
    }
#pragma unroll
    for (int off = 16; off; off >>= 1)
        mx = fmaxf(mx, __shfl_xor_sync(0xffffffffu, mx, off));

    // Dual-rank bisection for ascending order stats v[632] / v[633]
    float lo1 = 0.0f, hi1 = mx + 1e-3f;  // -> v[633]
    float lo2 = 0.0f, hi2 = hi1;         // -> v[632]
    for (int it = 0; it < 24; it++) {
        const float m1 = 0.5f * (lo1 + hi1);
        const float m2 = 0.5f * (lo2 + hi2);
        int cnt = 0;
#pragma unroll
        for (int k = 0; k < NPER; k++) {
            cnt += (r[k] > m1) ? 1 : 0;
            cnt += (r[k] > m2) ? 0x10000 : 0;
        }
#pragma unroll
        for (int off = 16; off; off >>= 1)
            cnt += __shfl_xor_sync(0xffffffffu, cnt, off);
        if ((cnt & 0xffff) >= 71) lo1 = m1; else hi1 = m1;
        if ((cnt >> 16)    >= 72) lo2 = m2; else hi2 = m2;
    }
    const float v71 = 0.5f * (lo1 + hi1);
    const float v72 = 0.5f * (lo2 + hi2);
    const float thr = fmaf(0.7f, v71 - v72, v72);

    __nv_bfloat16* rh = g_rate_hi + (size_t)sample * NOSC;
    __nv_bfloat16* rl = g_rate_lo + (size_t)sample * NOSC;
#pragma unroll
    for (int k = 0; k < NPER; k++) {
        const float z = (r[k] - thr) * 10.0f;
        const float sig = __fdividef(1.0f, 1.0f + __expf(-z));
        const float v = r[k] * sig;
        const __nv_bfloat16 h = __float2bfloat16(v);
        rh[k * 32 + lane] = h;
        rl[k * 32 + lane] = __float2bfloat16(v - __bfloat162float(h));
    }
}

// ---------------------------------------------------------------------------
// Kernel 2: bf16 split GEMM via family-common mma.sync.
// CTA tile 128M x 128N, BK=64 (11 chunks). 8 warps = 2(M) x 4(N), each warp
// 64x32 via m16n8k16 frags. Smem rows padded to 144B (conflict-free).
// 3-stage cp.async pipeline (221184 B smem).
// ---------------------------------------------------------------------------
#define BM 128
#define BN 128
#define BKC 64
#define NCH (KDIM / BKC)       // 11
#define RSB 144                 // smem row stride bytes (128B data + 16 pad)
#define TILE_B (128 * RSB)      // 18432 B
#define BUF_B  (4 * TILE_B)     // Ah, Al, Bh, Bl = 73728 B
#define GEMM_SMEM (3 * BUF_B)   // 221184 B (3-stage)

__global__ __launch_bounds__(256, 1) void gemm_kernel(const float* __restrict__ bias,
                                                      float* __restrict__ out) {
    extern __shared__ char smem[];
    const uint32_t sb = smem_u32(smem);
    const int t = threadIdx.x;
    const int wid = t >> 5;
    const int lane = t & 31;
    const int n0 = blockIdx.x * BN;
    const int m0 = blockIdx.y * BM;
    const int wm = (wid & 1) * 64;   // warp M offset
    const int wn = (wid >> 1) * 32;  // warp N offset

    const __nv_bfloat16* Ah = g_rate_hi + (size_t)m0 * KDIM;
    const __nv_bfloat16* Al = g_rate_lo + (size_t)m0 * KDIM;
    const __nv_bfloat16* Bh = g_W_hi + (size_t)n0 * KDIM;
    const __nv_bfloat16* Bl = g_W_lo + (size_t)n0 * KDIM;

    // per-chunk async load: 4 tiles x 128 rows x 8 segs(16B) = 4096 cp.async/CTA
    auto issue = [&](int kc, int buf) {
        const uint32_t bb = sb + buf * BUF_B;
        const int kb = kc * BKC;
#pragma unroll
        for (int i = 0; i < 4; i++) {
            const int u = i * 256 + t;          // 0..1023
            const int row = u >> 3, seg = u & 7;
            const uint32_t so = row * RSB + seg * 16;
            const size_t go = (size_t)row * KDIM + kb + seg * 8;
            cp16(bb + so,              Ah + go);
            cp16(bb + TILE_B + so,     Al + go);
            cp16(bb + 2 * TILE_B + so, Bh + go);
            cp16(bb + 3 * TILE_B + so, Bl + go);
        }
        CP_COMMIT();
    };

    float acc[4][4][4];
#pragma unroll
    for (int mf = 0; mf < 4; mf++)
#pragma unroll
        for (int nf = 0; nf < 4; nf++)
#pragma unroll
            for (int e = 0; e < 4; e++) acc[mf][nf][e] = 0.0f;

    issue(0, 0);
    issue(1, 1);

#pragma unroll 1
    for (int kc = 0; kc < NCH; kc++) {
        const int buf = kc % 3;
        if (kc + 2 < NCH) {
            issue(kc + 2, (kc + 2) % 3);
            asm volatile("cp.async.wait_group 2;" ::: "memory");
        } else if (kc + 1 < NCH) {
            asm volatile("cp.async.wait_group 1;" ::: "memory");
        } else {
            asm volatile("cp.async.wait_group 0;" ::: "memory");
        }
        __syncthreads();

        const uint32_t base = sb + buf * BUF_B;
#pragma unroll
        for (int ks = 0; ks < 4; ks++) {
            uint32_t ah[4][4], al[4][4], bh[4][2], bl[4][2];
            // A frags: lanes 0-15 -> rows, lane>>4 selects k-half (16B)
#pragma unroll
            for (int mf = 0; mf < 4; mf++) {
                const uint32_t ad = base + (wm + mf * 16 + (lane & 15)) * RSB +
                                    (lane >> 4) * 16 + ks * 32;
                ldsm4(ah[mf], ad);
                ldsm4(al[mf], ad + TILE_B);
            }
            // B frags: n = wn + nh*16 + ((lane>>4)<<3) + (lane&7),
            //          k-half = (lane>>3)&1
#pragma unroll
            for (int nh = 0; nh < 2; nh++) {
                const uint32_t bd = base + 2 * TILE_B +
                                    (wn + nh * 16 + ((lane >> 4) << 3) + (lane & 7)) * RSB +
                                    ((lane >> 3) & 1) * 16 + ks * 32;
                uint32_t r[4];
                ldsm4(r, bd);
                bh[nh * 2][0] = r[0]; bh[nh * 2][1] = r[1];
                bh[nh * 2 + 1][0] = r[2]; bh[nh * 2 + 1][1] = r[3];
                ldsm4(r, bd + TILE_B);
                bl[nh * 2][0] = r[0]; bl[nh * 2][1] = r[1];
                bl[nh * 2 + 1][0] = r[2]; bl[nh * 2 + 1][1] = r[3];
            }
#pragma unroll
            for (int mf = 0; mf < 4; mf++)
#pragma unroll
                for (int nf = 0; nf < 4; nf++) {
                    mma16816(acc[mf][nf], ah[mf], bh[nf]);
                    mma16816(acc[mf][nf], ah[mf], bl[nf]);
                    mma16816(acc[mf][nf], al[mf], bh[nf]);
                }
        }
        __syncthreads();
    }

    // epilogue: +bias, direct v2 stores (4-lane groups cover 32B contiguous)
#pragma unroll
    for (int nf = 0; nf < 4; nf++) {
        const int nbase = n0 + wn + nf * 8;       // NCLS = 1000 = 125*8
        if (nbase >= NCLS) continue;
        const int col = nbase + (lane & 3) * 2;
        const float b0 = bias[col], b1 = bias[col + 1];
#pragma unroll
        for (int mf = 0; mf < 4; mf++) {
            const int row = m0 + wm + mf * 16 + (lane >> 2);
            float2 v0 = make_float2(acc[mf][nf][0] + b0, acc[mf][nf][1] + b1);
            float2 v1 = make_float2(acc[mf][nf][2] + b0, acc[mf][nf][3] + b1);
            *(float2*)(out + (size_t)row * NCLS + col) = v0;
            *(float2*)(out + (size_t)(row + 8) * NCLS + col) = v1;
        }
    }
}

// ---------------------------------------------------------------------------
// Launch
// ---------------------------------------------------------------------------
extern "C" void kernel_launch(void* const* d_in, const int* in_sizes, int n_in,
                              void* d_out, int out_size) {
    const float* x  = (const float*)d_in[0];   // (65536, 704)
    const float* p0 = (const float*)d_in[1];   // (65536, 704)
    const float* W  = (const float*)d_in[2];   // (1000, 704)
    const float* b  = (const float*)d_in[3];   // (1000,)
    float* out = (float*)d_out;                // (65536, 1000)

    cudaFuncSetAttribute(gemm_kernel, cudaFuncAttributeMaxDynamicSharedMemorySize,
                         GEMM_SMEM);

    dyn_kernel<<<NSAMP / 8, 256>>>(x, p0, W);
    gemm_kernel<<<dim3(NPAD / BN, NSAMP / BM), 256, GEMM_SMEM>>>(b, out);
}